// round 12
// baseline (speedup 1.0000x reference)
#include <cuda_runtime.h>
#include <math.h>
#include <stdint.h>

// Problem constants
#define SEQ   512
#define BATCH 64
#define HID   1024
#define NIN   512
#define NOUT  512
#define NCTA  128     // recurrence grid: 8 j-tiles(128) x 16 k-chunks(64)
#define NJT   8
#define NKC   16
#define BH    (BATCH * HID)

// Scratch (device globals). Layout of xi/h: [s][b][h]
__device__ float g_xi[(size_t)SEQ * BATCH * HID];
__device__ float g_h [(size_t)SEQ * BATCH * HID];
// Partials per chain, parity double-buffered: [chain][par][kc*32 rows][HID]
__device__ float g_part2[2][2][(size_t)NKC * 32 * HID];

// Dataflow counters per chain (monotonic within launch; reset before replay)
__device__ unsigned g_grp2 [2][NJT * 32];
__device__ unsigned g_done2[2][NJT * 32];

__global__ void reset_barriers()
{
    if (threadIdx.x < NJT) {
        g_grp2 [0][threadIdx.x << 5] = 0;
        g_grp2 [1][threadIdx.x << 5] = 0;
        g_done2[0][threadIdx.x << 5] = 0;
        g_done2[1][threadIdx.x << 5] = 0;
    }
}

__device__ __forceinline__ unsigned ld_acq(const unsigned* p)
{
    unsigned v;
    asm volatile("ld.acquire.gpu.global.u32 %0, [%1];" : "=r"(v) : "l"(p));
    return v;
}
__device__ __forceinline__ void arrive(unsigned* p)
{
    asm volatile("red.release.gpu.global.add.u32 [%0], 1;" :: "l"(p) : "memory");
}

// ---------------------------------------------------------------------------
// 128x128x8 fp32 SGEMM with bias + output-row permutation (proven).
// PERM=1: A row m=(b*512+s) -> C row (s*64+b)   [GEMM1: x->xi]
// PERM=2: A row m=(s*64+b)  -> C row (b*512+s)  [GEMM3: h->y]
// ---------------------------------------------------------------------------
template<int K, int N, int PERM>
__global__ __launch_bounds__(256, 2) void gemm128(
    const float* __restrict__ A, const float* __restrict__ Bm,
    const float* __restrict__ bias, float* __restrict__ C)
{
    __shared__ float As[8][132];
    __shared__ float Bs[8][128];

    const int tid = threadIdx.x;
    const int tx = tid & 15, ty = tid >> 4;
    const int row0 = blockIdx.y * 128, col0 = blockIdx.x * 128;

    const int a_r = tid >> 1, a_k = (tid & 1) << 2;
    const int b_k = tid >> 5, b_c = (tid & 31) << 2;

    const float* Ap = A + (size_t)(row0 + a_r) * K + a_k;
    const float* Bp = Bm + (size_t)b_k * N + col0 + b_c;

    float4 ar = *(const float4*)Ap;
    float4 br = *(const float4*)Bp;

    float acc[8][8] = {};

    for (int k0 = 0; k0 < K; k0 += 8) {
        As[a_k + 0][a_r] = ar.x;
        As[a_k + 1][a_r] = ar.y;
        As[a_k + 2][a_r] = ar.z;
        As[a_k + 3][a_r] = ar.w;
        *(float4*)&Bs[b_k][b_c] = br;
        __syncthreads();
        if (k0 + 8 < K) {
            ar = *(const float4*)(Ap + k0 + 8);
            br = *(const float4*)(Bp + (size_t)(k0 + 8) * N);
        }
#pragma unroll
        for (int kk = 0; kk < 8; kk++) {
            float4 a0 = *(const float4*)&As[kk][ty << 2];
            float4 a1 = *(const float4*)&As[kk][(ty << 2) + 64];
            float4 b0 = *(const float4*)&Bs[kk][tx << 2];
            float4 b1 = *(const float4*)&Bs[kk][(tx << 2) + 64];
            float av[8] = {a0.x, a0.y, a0.z, a0.w, a1.x, a1.y, a1.z, a1.w};
            float bv[8] = {b0.x, b0.y, b0.z, b0.w, b1.x, b1.y, b1.z, b1.w};
#pragma unroll
            for (int i = 0; i < 8; i++)
#pragma unroll
                for (int j = 0; j < 8; j++)
                    acc[i][j] = fmaf(av[i], bv[j], acc[i][j]);
        }
        __syncthreads();
    }

    float4 bb0 = *(const float4*)&bias[col0 + (tx << 2)];
    float4 bb1 = *(const float4*)&bias[col0 + (tx << 2) + 64];
#pragma unroll
    for (int i = 0; i < 8; i++) {
        const int mloc = (i < 4) ? ((ty << 2) + i) : ((ty << 2) + i + 60);
        const int m = row0 + mloc;
        size_t r;
        if (PERM == 1)      r = (size_t)((m & 511) * 64 + (m >> 9));
        else if (PERM == 2) r = (size_t)((m & 63) * 512 + (m >> 6));
        else                r = (size_t)m;
        float* Cr = C + r * N + col0;
        float4 o0 = make_float4(acc[i][0] + bb0.x, acc[i][1] + bb0.y,
                                acc[i][2] + bb0.z, acc[i][3] + bb0.w);
        float4 o1 = make_float4(acc[i][4] + bb1.x, acc[i][5] + bb1.y,
                                acc[i][6] + bb1.z, acc[i][7] + bb1.w);
        *(float4*)(Cr + (tx << 2)) = o0;
        *(float4*)(Cr + (tx << 2) + 64) = o1;
    }
}

// ---------------------------------------------------------------------------
// Persistent recurrence, TWO interleaved independent batch-chains (32 rows
// each). CTA = (jt = bx&7 -> 128 cols, kc = bx>>3 -> 64 k's), 128 threads.
// Per step t, program order: A0 A1 B0 B1 — each chain's sync latency hides
// behind the other chain's compute. Counters per chain; partials per chain
// parity double-buffered (round-7 WAR argument holds per chain).
// ---------------------------------------------------------------------------
__global__ __launch_bounds__(128) void rnn_recurrence(const float* __restrict__ Wh)
{
    __shared__ float As[16][36];    // k x row(32); 144B rows (16B-aligned)
    __shared__ float Bs[64][128];   // persistent Wh slice [k][j], 32KB

    const int tid = threadIdx.x;
    const int jt = blockIdx.x & 7;
    const int kc = blockIdx.x >> 3;
    const int col0 = jt << 7;
    const int kbase = kc << 6;
    const int tx = tid & 15, ty = tid >> 4;       // ty 0..7
    const int a_r = tid >> 2, a_k = (tid & 3) << 2;  // 32 rows x 16 k
    const int src = (kc >> 1) << 5;
    const int own = jt << 5;

    // Load persistent Wh slice (64 k x 128 j)
#pragma unroll
    for (int i = 0; i < 16; i++) {
        int e4 = i * 128 + tid;
        int k = e4 >> 5, c = (e4 & 31) << 2;
        *(float4*)&Bs[k][c] = *(const float4*)&Wh[(size_t)(kbase + k) * HID + col0 + c];
    }

    // h_0 init, both chains: rows 32c + 2kc + (tid>>6), cols [128jt..+128)
#pragma unroll
    for (int c = 0; c < 2; c++) {
        const int b = c * 32 + (kc << 1) + (tid >> 6);
        const int cc = col0 + ((tid & 63) << 1);
        const size_t off = (size_t)b * HID + cc;
        float2 v = *(const float2*)&g_xi[off];
        v.x = fmaxf(tanhf(v.x), 0.0f);
        v.y = fmaxf(tanhf(v.y), 0.0f);
        *(float2*)&g_h[off] = v;
    }
    __syncthreads();
    if (tid == 0) {
        arrive(&g_done2[0][own]);
        arrive(&g_done2[1][own]);
    }

    for (int t = 1; t < SEQ; t++) {
        const unsigned target = (unsigned)(NKC * t);

        // ================= phase A, chains 0 then 1 =================
#pragma unroll
        for (int c = 0; c < 2; c++) {
            if (tid == 0) {
                while (ld_acq(&g_done2[c][src]) < target) {}
            }
            __syncthreads();

            const float* hprev = g_h + (size_t)(t - 1) * BH + (size_t)c * 32 * HID;
            float acc[4][8] = {};

            float4 av = *(const float4*)&hprev[(size_t)a_r * HID + kbase + a_k];
            for (int k0 = 0; k0 < 64; k0 += 16) {
                As[a_k + 0][a_r] = av.x;
                As[a_k + 1][a_r] = av.y;
                As[a_k + 2][a_r] = av.z;
                As[a_k + 3][a_r] = av.w;
                __syncthreads();
                if (k0 + 16 < 64)
                    av = *(const float4*)&hprev[(size_t)a_r * HID + kbase + k0 + 16 + a_k];
#pragma unroll
                for (int kk = 0; kk < 16; kk++) {
                    float4 a = *(const float4*)&As[kk][ty << 2];
                    float4 b0 = *(const float4*)&Bs[k0 + kk][tx << 3];
                    float4 b1 = *(const float4*)&Bs[k0 + kk][(tx << 3) + 4];
                    float avf[4] = {a.x, a.y, a.z, a.w};
                    float bvf[8] = {b0.x, b0.y, b0.z, b0.w, b1.x, b1.y, b1.z, b1.w};
#pragma unroll
                    for (int i = 0; i < 4; i++)
#pragma unroll
                        for (int j = 0; j < 8; j++)
                            acc[i][j] = fmaf(avf[i], bvf[j], acc[i][j]);
                }
                __syncthreads();
            }

            float* part = g_part2[c][t & 1];
#pragma unroll
            for (int i = 0; i < 4; i++) {
                const int r = (ty << 2) + i;            // row within 32
                float* pp = &part[((size_t)kc * 32 + r) * HID + col0 + (tx << 3)];
                *(float4*)pp = make_float4(acc[i][0], acc[i][1], acc[i][2], acc[i][3]);
                *(float4*)(pp + 4) = make_float4(acc[i][4], acc[i][5], acc[i][6], acc[i][7]);
            }
            __syncthreads();
            if (tid == 0) arrive(&g_grp2[c][own]);
        }

        // ================= phase B, chains 0 then 1 =================
#pragma unroll
        for (int c = 0; c < 2; c++) {
            if (tid == 0) {
                while (ld_acq(&g_grp2[c][own]) < target) {}
            }
            __syncthreads();

            const int r32 = (kc << 1) + (tid >> 6);     // row within 32
            const int b = c * 32 + r32;
            const int cc = col0 + ((tid & 63) << 1);
            const size_t off = (size_t)t * BH + (size_t)b * HID + cc;
            float2 v = *(const float2*)&g_xi[off];
            const float* part = g_part2[c][t & 1];
#pragma unroll
            for (int q = 0; q < NKC; q++) {
                float2 p = *(const float2*)&part[((size_t)q * 32 + r32) * HID + cc];
                v.x += p.x; v.y += p.y;
            }
            v.x = fmaxf(tanhf(v.x), 0.0f);
            v.y = fmaxf(tanhf(v.y), 0.0f);
            *(float2*)&g_h[off] = v;
            __syncthreads();
            if (tid == 0) arrive(&g_done2[c][own]);
        }
    }
}

// ---------------------------------------------------------------------------
extern "C" void kernel_launch(void* const* d_in, const int* in_sizes, int n_in,
                              void* d_out, int out_size)
{
    const float* x  = (const float*)d_in[0];
    const float* Wi = (const float*)d_in[1];
    const float* bi = (const float*)d_in[2];
    const float* Wh = (const float*)d_in[3];
    const float* Wo = (const float*)d_in[4];
    const float* bo = (const float*)d_in[5];
    float* out = (float*)d_out;

    void* p;
    cudaGetSymbolAddress(&p, g_xi);
    float* xi = (float*)p;
    cudaGetSymbolAddress(&p, g_h);
    float* hh = (float*)p;

    // 0) zero dataflow counters so every graph replay starts clean
    reset_barriers<<<1, 32>>>();

    // 1) xi[s][b][h] = x @ Wi + bi   (fp32, ~roofline)
    gemm128<NIN, HID, 1><<<dim3(HID / 128, (BATCH * SEQ) / 128), 256>>>(x, Wi, bi, xi);

    // 2) recurrence: one persistent kernel, two interleaved batch-chains
    rnn_recurrence<<<NCTA, 128>>>(Wh);

    // 3) y[b][s][o] = h @ Wo + bo    (fp32, ~roofline)
    gemm128<HID, NOUT, 2><<<dim3(NOUT / 128, (BATCH * SEQ) / 128), 256>>>(hh, Wo, bo, out);
}

// round 13
// speedup vs baseline: 1.4217x; 1.4217x over previous
#include <cuda_runtime.h>
#include <math.h>
#include <stdint.h>

// Problem constants
#define SEQ   512
#define BATCH 64
#define HID   1024
#define NIN   512
#define NOUT  512
#define NCTA  128     // recurrence grid: 8 j-tiles(128) x 16 k-chunks(64)
#define NJT   8
#define NKC   16
#define BH    (BATCH * HID)

// Scratch (device globals). Layout of xi/h: [s][b][h]
__device__ float g_xi[(size_t)SEQ * BATCH * HID];
__device__ float g_h [(size_t)SEQ * BATCH * HID];
__device__ float g_part[2][NKC * BATCH * HID];    // parity double-buffered partials

// Dataflow counters (monotonic within a launch; reset node before each replay)
__device__ unsigned g_grp [NJT * 32];
__device__ unsigned g_done[NJT * 32];

__global__ void reset_barriers()
{
    if (threadIdx.x < NJT) {
        g_grp [threadIdx.x << 5] = 0;
        g_done[threadIdx.x << 5] = 0;
    }
}

__device__ __forceinline__ unsigned ld_acq(const unsigned* p)
{
    unsigned v;
    asm volatile("ld.acquire.gpu.global.u32 %0, [%1];" : "=r"(v) : "l"(p));
    return v;
}
__device__ __forceinline__ void arrive(unsigned* p)
{
    asm volatile("red.release.gpu.global.add.u32 [%0], 1;" :: "l"(p) : "memory");
}
__device__ __forceinline__ float tf32_hi(float a)
{
    uint32_t u;
    asm("cvt.rna.tf32.f32 %0, %1;" : "=r"(u) : "f"(a));
    return __uint_as_float(u);
}

// mma.sync m16n8k8 tf32 (fragment mapping validated rounds 9-10)
#define MMA_TF32(c, a, b)                                                   \
    asm volatile("mma.sync.aligned.m16n8k8.row.col.f32.tf32.tf32.f32 "      \
        "{%0,%1,%2,%3}, {%4,%5,%6,%7}, {%8,%9}, {%0,%1,%2,%3};"             \
        : "+f"((c)[0]), "+f"((c)[1]), "+f"((c)[2]), "+f"((c)[3])            \
        : "r"((a)[0]), "r"((a)[1]), "r"((a)[2]), "r"((a)[3]),               \
          "r"((b)[0]), "r"((b)[1]))

// ---------------------------------------------------------------------------
// 3xTF32 mma.sync GEMM with fragment-ordered fp32 staging.
// Block tile 128x128, K-tile 16, 8 warps (2m x 4n), warp tile 64x32.
// Smem layout (fragment order, storage slot = tig*8+gid):
//   Af[ks][mt][slot]  float4 {a0,a1,a2,a3}  (raw fp32; hi/lo split at use)
//   Bf[ks][nt][slot]  float2 {b0,b1}        (nt blocks padded to 33)
// PERM=1: A row m=(b*512+s) -> C row (s*64+b)   [GEMM1: x->xi]
// PERM=2: A row m=(s*64+b)  -> C row (b*512+s)  [GEMM3: h->y]
// ---------------------------------------------------------------------------
template<int K, int N, int PERM>
__global__ __launch_bounds__(256, 2) void gemm_tc(
    const float* __restrict__ A, const float* __restrict__ Bm,
    const float* __restrict__ bias, float* __restrict__ C)
{
    __shared__ float4 Af[2][8][32];     // 8 KB
    __shared__ float2 Bf[2][16][33];    // 8.25 KB (pad kills nt bank overlap)

    const int tid  = threadIdx.x;
    const int lane = tid & 31, wid = tid >> 5;
    const int gid  = lane >> 2, tig = lane & 3;
    const int wm = wid & 1, wn = wid >> 1;
    const int row0 = blockIdx.y * 128, col0 = blockIdx.x * 128;
    const int mtb = wm * 4, ntb = wn * 4;
    const int fslot = tig * 8 + gid;           // fragment storage slot

    // A staging map: thread -> row ra, k-step aks; 8 consecutive k floats
    const int ra = tid >> 1, aks = tid & 1;
    const int gidA = ra & 7, rhi = (ra >> 3) & 1, mtA = ra >> 4;
    // B staging map: thread -> k-row kr, n-tile ntB; 8 consecutive n floats
    const int kr = tid >> 4, bks = kr >> 3, kkB = kr & 7;
    const int tigB = kkB & 3, compB = kkB >> 2;
    const int ntB = tid & 15;

    const float* Ap = A + (size_t)(row0 + ra) * K + aks * 8;
    const float* Bp = Bm + (size_t)kr * N + col0 + ntB * 8;

    float4 ga0 = *(const float4*)Ap;
    float4 ga1 = *(const float4*)(Ap + 4);
    float4 gb0 = *(const float4*)Bp;
    float4 gb1 = *(const float4*)(Bp + 4);

    float c[4][4][4] = {};                     // [mtile][ntile][reg]

    for (int k0 = 0; k0 < K; k0 += 16) {
        // ---- stage into fragment-ordered smem (raw fp32) ----
        {
            float va[8] = {ga0.x, ga0.y, ga0.z, ga0.w, ga1.x, ga1.y, ga1.z, ga1.w};
            float* dstA = (float*)&Af[aks][mtA][0];
#pragma unroll
            for (int j = 0; j < 8; j++) {
                const int slot = (j & 3) * 8 + gidA;
                const int comp = ((j >> 2) << 1) | rhi;
                dstA[slot * 4 + comp] = va[j];
            }
            float vb[8] = {gb0.x, gb0.y, gb0.z, gb0.w, gb1.x, gb1.y, gb1.z, gb1.w};
            float* dstB = (float*)&Bf[bks][ntB][0];
#pragma unroll
            for (int e = 0; e < 8; e++)
                dstB[(tigB * 8 + e) * 2 + compB] = vb[e];
        }
        __syncthreads();

        if (k0 + 16 < K) {
            ga0 = *(const float4*)(Ap + k0 + 16);
            ga1 = *(const float4*)(Ap + k0 + 20);
            gb0 = *(const float4*)(Bp + (size_t)(k0 + 16) * N);
            gb1 = *(const float4*)(Bp + (size_t)(k0 + 16) * N + 4);
        }

        // ---- MMA: 2 ksteps x 4 mtiles x 4 ntiles x 3 (hh + hl + lh) ----
#pragma unroll
        for (int ks = 0; ks < 2; ks++) {
            uint32_t ah[4][4], al[4][4];
#pragma unroll
            for (int i = 0; i < 4; i++) {
                float4 af = Af[ks][mtb + i][fslot];
                float h;
                h = tf32_hi(af.x); ah[i][0] = __float_as_uint(h); al[i][0] = __float_as_uint(af.x - h);
                h = tf32_hi(af.y); ah[i][1] = __float_as_uint(h); al[i][1] = __float_as_uint(af.y - h);
                h = tf32_hi(af.z); ah[i][2] = __float_as_uint(h); al[i][2] = __float_as_uint(af.z - h);
                h = tf32_hi(af.w); ah[i][3] = __float_as_uint(h); al[i][3] = __float_as_uint(af.w - h);
            }
#pragma unroll
            for (int j = 0; j < 4; j++) {
                float2 bf = Bf[ks][ntb + j][fslot];
                float h0 = tf32_hi(bf.x), h1 = tf32_hi(bf.y);
                uint32_t bh[2] = {__float_as_uint(h0), __float_as_uint(h1)};
                uint32_t bl[2] = {__float_as_uint(bf.x - h0), __float_as_uint(bf.y - h1)};
#pragma unroll
                for (int i = 0; i < 4; i++) {
                    MMA_TF32(c[i][j], ah[i], bh);
                    MMA_TF32(c[i][j], ah[i], bl);
                    MMA_TF32(c[i][j], al[i], bh);
                }
            }
        }
        __syncthreads();
    }

    // ---- epilogue: bias + permuted row store (round-9 validated) ----
#pragma unroll
    for (int i = 0; i < 4; i++) {
        const int m_lo = row0 + wm * 64 + i * 16 + gid;
        const int m_hi = m_lo + 8;
        size_t r_lo, r_hi;
        if (PERM == 1) {
            r_lo = (size_t)((m_lo & 511) * 64 + (m_lo >> 9));
            r_hi = (size_t)((m_hi & 511) * 64 + (m_hi >> 9));
        } else {
            r_lo = (size_t)((m_lo & 63) * 512 + (m_lo >> 6));
            r_hi = (size_t)((m_hi & 63) * 512 + (m_hi >> 6));
        }
#pragma unroll
        for (int j = 0; j < 4; j++) {
            const int col = col0 + wn * 32 + j * 8 + 2 * tig;
            const float b0 = bias[col], b1 = bias[col + 1];
            *(float2*)&C[r_lo * N + col] = make_float2(c[i][j][0] + b0, c[i][j][1] + b1);
            *(float2*)&C[r_hi * N + col] = make_float2(c[i][j][2] + b0, c[i][j][3] + b1);
        }
    }
}

// ---------------------------------------------------------------------------
// Persistent recurrence (byte-exact round-7 config: best measured, 5557us)
// ---------------------------------------------------------------------------
__global__ __launch_bounds__(128) void rnn_recurrence(const float* __restrict__ Wh)
{
    __shared__ float As[16][68];
    __shared__ float Bs[64][128];

    const int tid = threadIdx.x;
    const int jt = blockIdx.x & 7;
    const int kc = blockIdx.x >> 3;
    const int col0 = jt << 7;
    const int kbase = kc << 6;
    const int tx = tid & 15, ty = tid >> 4;
    const int a_r = tid >> 1, a_k8 = (tid & 1) << 3;
    const int src = (kc >> 1) << 5;
    const int own = jt << 5;

#pragma unroll
    for (int i = 0; i < 16; i++) {
        int e4 = i * 128 + tid;
        int k = e4 >> 5, c = (e4 & 31) << 2;
        *(float4*)&Bs[k][c] = *(const float4*)&Wh[(size_t)(kbase + k) * HID + col0 + c];
    }

    {
        const int b = (kc << 2) + (tid >> 5);
        const int c = col0 + ((tid & 31) << 2);
        const size_t off = (size_t)b * HID + c;
        float4 v = *(const float4*)&g_xi[off];
        v.x = fmaxf(tanhf(v.x), 0.0f);
        v.y = fmaxf(tanhf(v.y), 0.0f);
        v.z = fmaxf(tanhf(v.z), 0.0f);
        v.w = fmaxf(tanhf(v.w), 0.0f);
        *(float4*)&g_h[off] = v;
    }
    __syncthreads();
    if (tid == 0) arrive(&g_done[own]);

    for (int t = 1; t < SEQ; t++) {
        if (tid == 0) {
            const unsigned target = (unsigned)(NKC * t);
            while (ld_acq(&g_done[src]) < target) {}
        }
        __syncthreads();

        const float* hprev = g_h + (size_t)(t - 1) * BH;
        float* part = g_part[t & 1];
        float acc[8][8] = {};

        const float* hrow = hprev + (size_t)a_r * HID + kbase + a_k8;
        float4 pa0 = *(const float4*)hrow;
        float4 pa1 = *(const float4*)(hrow + 4);

        for (int k0 = 0; k0 < 64; k0 += 16) {
            As[a_k8 + 0][a_r] = pa0.x;
            As[a_k8 + 1][a_r] = pa0.y;
            As[a_k8 + 2][a_r] = pa0.z;
            As[a_k8 + 3][a_r] = pa0.w;
            As[a_k8 + 4][a_r] = pa1.x;
            As[a_k8 + 5][a_r] = pa1.y;
            As[a_k8 + 6][a_r] = pa1.z;
            As[a_k8 + 7][a_r] = pa1.w;
            __syncthreads();
            if (k0 + 16 < 64) {
                pa0 = *(const float4*)(hrow + k0 + 16);
                pa1 = *(const float4*)(hrow + k0 + 20);
            }
#pragma unroll
            for (int kk = 0; kk < 16; kk++) {
                float4 a0 = *(const float4*)&As[kk][ty << 3];
                float4 a1 = *(const float4*)&As[kk][(ty << 3) + 4];
                float4 b0 = *(const float4*)&Bs[k0 + kk][tx << 3];
                float4 b1 = *(const float4*)&Bs[k0 + kk][(tx << 3) + 4];
                float av[8] = {a0.x, a0.y, a0.z, a0.w, a1.x, a1.y, a1.z, a1.w};
                float bv[8] = {b0.x, b0.y, b0.z, b0.w, b1.x, b1.y, b1.z, b1.w};
#pragma unroll
                for (int i = 0; i < 8; i++)
#pragma unroll
                    for (int j = 0; j < 8; j++)
                        acc[i][j] = fmaf(av[i], bv[j], acc[i][j]);
            }
            __syncthreads();
        }

#pragma unroll
        for (int i = 0; i < 8; i++) {
            const int b = (ty << 3) + i;
            float* pp = &part[(size_t)kc * BH + (size_t)b * HID + col0 + (tx << 3)];
            *(float4*)pp = make_float4(acc[i][0], acc[i][1], acc[i][2], acc[i][3]);
            *(float4*)(pp + 4) = make_float4(acc[i][4], acc[i][5], acc[i][6], acc[i][7]);
        }
        __syncthreads();

        if (tid == 0) {
            arrive(&g_grp[own]);
            const unsigned target = (unsigned)(NKC * t);
            while (ld_acq(&g_grp[own]) < target) {}
        }
        __syncthreads();

        {
            const int b = (kc << 2) + (tid >> 5);
            const int cc = col0 + ((tid & 31) << 2);
            const size_t eo = (size_t)b * HID + cc;
            const size_t off = (size_t)t * BH + eo;
            float4 v = *(const float4*)&g_xi[off];
#pragma unroll
            for (int q = 0; q < NKC; q++) {
                float4 p = *(const float4*)&part[(size_t)q * BH + eo];
                v.x += p.x; v.y += p.y; v.z += p.z; v.w += p.w;
            }
            v.x = fmaxf(tanhf(v.x), 0.0f);
            v.y = fmaxf(tanhf(v.y), 0.0f);
            v.z = fmaxf(tanhf(v.z), 0.0f);
            v.w = fmaxf(tanhf(v.w), 0.0f);
            *(float4*)&g_h[off] = v;
        }
        __syncthreads();
        if (tid == 0) arrive(&g_done[own]);
    }
}

// ---------------------------------------------------------------------------
extern "C" void kernel_launch(void* const* d_in, const int* in_sizes, int n_in,
                              void* d_out, int out_size)
{
    const float* x  = (const float*)d_in[0];
    const float* Wi = (const float*)d_in[1];
    const float* bi = (const float*)d_in[2];
    const float* Wh = (const float*)d_in[3];
    const float* Wo = (const float*)d_in[4];
    const float* bo = (const float*)d_in[5];
    float* out = (float*)d_out;

    void* p;
    cudaGetSymbolAddress(&p, g_xi);
    float* xi = (float*)p;
    cudaGetSymbolAddress(&p, g_h);
    float* hh = (float*)p;

    // 0) zero dataflow counters so every graph replay starts clean
    reset_barriers<<<1, 32>>>();

    // 1) xi[s][b][h] = x @ Wi + bi   (3xTF32 mma.sync, fragment-staged)
    gemm_tc<NIN, HID, 1><<<dim3(HID / 128, (BATCH * SEQ) / 128), 256>>>(x, Wi, bi, xi);

    // 2) whole recurrence in one persistent kernel (round-7 proven)
    rnn_recurrence<<<NCTA, 128>>>(Wh);

    // 3) y[b][s][o] = h @ Wo + bo    (3xTF32 mma.sync, fragment-staged)
    gemm_tc<HID, NOUT, 2><<<dim3(NOUT / 128, (BATCH * SEQ) / 128), 256>>>(hh, Wo, bo, out);
}

// round 14
// speedup vs baseline: 1.5390x; 1.0825x over previous
#include <cuda_runtime.h>
#include <math.h>
#include <stdint.h>

// Problem constants
#define SEQ   512
#define BATCH 64
#define HID   1024
#define NIN   512
#define NOUT  512
#define BH    (BATCH * HID)
// Recurrence grid: 8 jt (128 cols) x 8 kc (128 k) x 2 bh (32 rows) = 128 CTAs
#define NKC   8

// Scratch (device globals). Layout of xi/h: [s][b][h]
__device__ float g_xi[(size_t)SEQ * BATCH * HID];
__device__ float g_h [(size_t)SEQ * BATCH * HID];
// Partials, parity double-buffered: [par][q 8][64 rows][1024 cols]
__device__ float g_part[2][NKC][BATCH][HID];

// Dataflow counters, one per (jt,bh) group, padded 128B apart.
// grp : phase-A completions; done : phase-B (h written) completions.
__device__ unsigned g_grp [16 * 32];
__device__ unsigned g_done[16 * 32];

__global__ void reset_barriers()
{
    if (threadIdx.x < 16) {
        g_grp [threadIdx.x << 5] = 0;
        g_done[threadIdx.x << 5] = 0;
    }
}

__device__ __forceinline__ unsigned ld_acq(const unsigned* p)
{
    unsigned v;
    asm volatile("ld.acquire.gpu.global.u32 %0, [%1];" : "=r"(v) : "l"(p));
    return v;
}
__device__ __forceinline__ void arrive(unsigned* p)
{
    asm volatile("red.release.gpu.global.add.u32 [%0], 1;" :: "l"(p) : "memory");
}

// ---------------------------------------------------------------------------
// 128x128x8 fp32 SGEMM with bias + output-row permutation (proven, ~roofline)
// PERM=1: A row m=(b*512+s) -> C row (s*64+b)   [GEMM1: x->xi]
// PERM=2: A row m=(s*64+b)  -> C row (b*512+s)  [GEMM3: h->y]
// ---------------------------------------------------------------------------
template<int K, int N, int PERM>
__global__ __launch_bounds__(256, 2) void gemm128(
    const float* __restrict__ A, const float* __restrict__ Bm,
    const float* __restrict__ bias, float* __restrict__ C)
{
    __shared__ float As[8][132];
    __shared__ float Bs[8][128];

    const int tid = threadIdx.x;
    const int tx = tid & 15, ty = tid >> 4;
    const int row0 = blockIdx.y * 128, col0 = blockIdx.x * 128;

    const int a_r = tid >> 1, a_k = (tid & 1) << 2;
    const int b_k = tid >> 5, b_c = (tid & 31) << 2;

    const float* Ap = A + (size_t)(row0 + a_r) * K + a_k;
    const float* Bp = Bm + (size_t)b_k * N + col0 + b_c;

    float4 ar = *(const float4*)Ap;
    float4 br = *(const float4*)Bp;

    float acc[8][8] = {};

    for (int k0 = 0; k0 < K; k0 += 8) {
        As[a_k + 0][a_r] = ar.x;
        As[a_k + 1][a_r] = ar.y;
        As[a_k + 2][a_r] = ar.z;
        As[a_k + 3][a_r] = ar.w;
        *(float4*)&Bs[b_k][b_c] = br;
        __syncthreads();
        if (k0 + 8 < K) {
            ar = *(const float4*)(Ap + k0 + 8);
            br = *(const float4*)(Bp + (size_t)(k0 + 8) * N);
        }
#pragma unroll
        for (int kk = 0; kk < 8; kk++) {
            float4 a0 = *(const float4*)&As[kk][ty << 2];
            float4 a1 = *(const float4*)&As[kk][(ty << 2) + 64];
            float4 b0 = *(const float4*)&Bs[kk][tx << 2];
            float4 b1 = *(const float4*)&Bs[kk][(tx << 2) + 64];
            float av[8] = {a0.x, a0.y, a0.z, a0.w, a1.x, a1.y, a1.z, a1.w};
            float bv[8] = {b0.x, b0.y, b0.z, b0.w, b1.x, b1.y, b1.z, b1.w};
#pragma unroll
            for (int i = 0; i < 8; i++)
#pragma unroll
                for (int j = 0; j < 8; j++)
                    acc[i][j] = fmaf(av[i], bv[j], acc[i][j]);
        }
        __syncthreads();
    }

    float4 bb0 = *(const float4*)&bias[col0 + (tx << 2)];
    float4 bb1 = *(const float4*)&bias[col0 + (tx << 2) + 64];
#pragma unroll
    for (int i = 0; i < 8; i++) {
        const int mloc = (i < 4) ? ((ty << 2) + i) : ((ty << 2) + i + 60);
        const int m = row0 + mloc;
        size_t r;
        if (PERM == 1)      r = (size_t)((m & 511) * 64 + (m >> 9));
        else if (PERM == 2) r = (size_t)((m & 63) * 512 + (m >> 6));
        else                r = (size_t)m;
        float* Cr = C + r * N + col0;
        float4 o0 = make_float4(acc[i][0] + bb0.x, acc[i][1] + bb0.y,
                                acc[i][2] + bb0.z, acc[i][3] + bb0.w);
        float4 o1 = make_float4(acc[i][4] + bb1.x, acc[i][5] + bb1.y,
                                acc[i][6] + bb1.z, acc[i][7] + bb1.w);
        *(float4*)(Cr + (tx << 2)) = o0;
        *(float4*)(Cr + (tx << 2) + 64) = o1;
    }
}

// ---------------------------------------------------------------------------
// Persistent recurrence, batch-split: CTA = (jt, kc, bh).
//   jt = bx&7 -> cols [128jt..+128), kc = (bx>>3)&7 -> k [128kc..+128),
//   bh = bx>>6 -> rows [32bh..+32).
// Phase A: wait done[kc][bh]>=8t (all-thread poll) -> 32x128x128 partial
//   GEMM (Wh slice resident, 64KB) -> store part[t&1][kc] -> arrive grp[jt][bh].
// Phase B: prefetch xi -> wait grp[jt][bh]>=8t -> reduce 4 rows x 128 cols
//   from 8 partials, tanh, relu -> g_h -> arrive done[jt][bh].
// ---------------------------------------------------------------------------
#define RNN_DSMEM ((16384 + 16 * 36) * 4)

__global__ __launch_bounds__(128) void rnn_recurrence(const float* __restrict__ Wh)
{
    extern __shared__ float dsm[];
    float* Bs = dsm;                 // [128 k][128 j]
    float* As = dsm + 16384;         // [16 k][36 rows] (144B rows, 16B-aligned)

    const int tid = threadIdx.x;
    const int jt = blockIdx.x & 7;
    const int kc = (blockIdx.x >> 3) & 7;
    const int bhh = blockIdx.x >> 6;
    const int col0 = jt << 7;
    const int kbase = kc << 7;
    const int rbase = bhh << 5;
    const int w  = tid >> 5;                 // warp id 0..3 -> 8 rows each
    const int tx = tid & 31;                 // 4 cols each
    const int a_r = tid >> 2, a_k = (tid & 3) << 2;
    const int own = ((jt << 1) | bhh) << 5;
    const int src = ((kc << 1) | bhh) << 5;

    // Load persistent Wh slice [128k][128j] (one-time, 64KB)
#pragma unroll
    for (int i = 0; i < 32; i++) {
        const int e4 = i * 128 + tid;                // float4 index
        const int k = e4 >> 5, c = (e4 & 31) << 2;
        *(float4*)&Bs[k * 128 + c] =
            *(const float4*)&Wh[(size_t)(kbase + k) * HID + col0 + c];
    }

    // h_0 init on this CTA's phase-B slice: rows rbase+4kc+(tid>>5), 128 cols
    {
        const int row = rbase + (kc << 2) + w;
        const int cc = col0 + (tx << 2);
        const size_t off = (size_t)row * HID + cc;
        float4 v = *(const float4*)&g_xi[off];
        v.x = fmaxf(tanhf(v.x), 0.0f);
        v.y = fmaxf(tanhf(v.y), 0.0f);
        v.z = fmaxf(tanhf(v.z), 0.0f);
        v.w = fmaxf(tanhf(v.w), 0.0f);
        *(float4*)&g_h[off] = v;
    }
    __syncthreads();
    if (tid == 0) arrive(&g_done[own]);

    for (int t = 1; t < SEQ; t++) {
        const unsigned target = 8u * (unsigned)t;

        // ---- A-wait: h(t-1) rows[rbase..+32) cols[kbase..+128) ready ----
        while (ld_acq(&g_done[src]) < target) {}

        // ---- phase A: 32x128 partial GEMM over 128-wide K chunk ----
        const float* hprev = g_h + (size_t)(t - 1) * BH;
        float acc[8][4] = {};

        const float* hrow = hprev + (size_t)(rbase + a_r) * HID + kbase + a_k;
        float4 pa = *(const float4*)hrow;

        for (int k0 = 0; k0 < 128; k0 += 16) {
            As[(a_k + 0) * 36 + a_r] = pa.x;
            As[(a_k + 1) * 36 + a_r] = pa.y;
            As[(a_k + 2) * 36 + a_r] = pa.z;
            As[(a_k + 3) * 36 + a_r] = pa.w;
            __syncthreads();
            if (k0 + 16 < 128)
                pa = *(const float4*)(hrow + k0 + 16);
#pragma unroll
            for (int kk = 0; kk < 16; kk++) {
                float4 a0 = *(const float4*)&As[(k0 ? kk : kk) * 36 + (w << 3)];
                float4 a1 = *(const float4*)&As[kk * 36 + (w << 3) + 4];
                float4 b  = *(const float4*)&Bs[(k0 + kk) * 128 + (tx << 2)];
                float av[8] = {a0.x, a0.y, a0.z, a0.w, a1.x, a1.y, a1.z, a1.w};
                float bv[4] = {b.x, b.y, b.z, b.w};
#pragma unroll
                for (int i = 0; i < 8; i++)
#pragma unroll
                    for (int j = 0; j < 4; j++)
                        acc[i][j] = fmaf(av[i], bv[j], acc[i][j]);
            }
            __syncthreads();
        }

        // store partials: rows rbase + w*8 + i, cols col0 + tx*4
        {
            float* pd = &g_part[t & 1][kc][0][0];
#pragma unroll
            for (int i = 0; i < 8; i++) {
                const int row = rbase + (w << 3) + i;
                *(float4*)&pd[(size_t)row * HID + col0 + (tx << 2)] =
                    make_float4(acc[i][0], acc[i][1], acc[i][2], acc[i][3]);
            }
        }
        __syncthreads();
        if (tid == 0) arrive(&g_grp[own]);

        // ---- phase B: reduce own 4-row slice from 8 partials ----
        {
            const int row = rbase + (kc << 2) + w;
            const int cc = col0 + (tx << 2);
            const size_t eo = (size_t)row * HID + cc;
            const size_t off = (size_t)t * BH + eo;
            float4 v = *(const float4*)&g_xi[off];   // prefetch before wait

            while (ld_acq(&g_grp[own]) < target) {}

            const float* pt = &g_part[t & 1][0][0][0];
#pragma unroll
            for (int q = 0; q < NKC; q++) {
                float4 p = *(const float4*)&pt[(size_t)q * BH + eo];
                v.x += p.x; v.y += p.y; v.z += p.z; v.w += p.w;
            }
            v.x = fmaxf(tanhf(v.x), 0.0f);
            v.y = fmaxf(tanhf(v.y), 0.0f);
            v.z = fmaxf(tanhf(v.z), 0.0f);
            v.w = fmaxf(tanhf(v.w), 0.0f);
            *(float4*)&g_h[off] = v;
        }
        __syncthreads();
        if (tid == 0) arrive(&g_done[own]);
    }
}

// ---------------------------------------------------------------------------
extern "C" void kernel_launch(void* const* d_in, const int* in_sizes, int n_in,
                              void* d_out, int out_size)
{
    const float* x  = (const float*)d_in[0];
    const float* Wi = (const float*)d_in[1];
    const float* bi = (const float*)d_in[2];
    const float* Wh = (const float*)d_in[3];
    const float* Wo = (const float*)d_in[4];
    const float* bo = (const float*)d_in[5];
    float* out = (float*)d_out;

    void* p;
    cudaGetSymbolAddress(&p, g_xi);
    float* xi = (float*)p;
    cudaGetSymbolAddress(&p, g_h);
    float* hh = (float*)p;

    cudaFuncSetAttribute(rnn_recurrence,
                         cudaFuncAttributeMaxDynamicSharedMemorySize, RNN_DSMEM);

    // 0) zero dataflow counters so every graph replay starts clean
    reset_barriers<<<1, 32>>>();

    // 1) xi[s][b][h] = x @ Wi + bi   (fp32, ~roofline)
    gemm128<NIN, HID, 1><<<dim3(HID / 128, (BATCH * SEQ) / 128), 256>>>(x, Wi, bi, xi);

    // 2) recurrence: batch-split persistent kernel (fan-in 8, half B-traffic)
    rnn_recurrence<<<128, 128, RNN_DSMEM>>>(Wh);

    // 3) y[b][s][o] = h @ Wo + bo    (fp32, ~roofline)
    gemm128<HID, NOUT, 2><<<dim3(NOUT / 128, (BATCH * SEQ) / 128), 256>>>(hh, Wo, bo, out);
}